// round 16
// baseline (speedup 1.0000x reference)
#include <cuda_runtime.h>
#include <math.h>
#include <stdint.h>

// ---------------------------------------------------------------------------
// Mamba2 block, B=2, T=1024, D_MODEL=2048, D_STATE=64, HEADDIM=64
// R14: fp32 FFMA2 pipeline. Deltas vs R13 (2458us):
//   - GEMM: persistent CTAs (kills 3.57-wave tail), BK=16 double-buffered
//     smem (1 barrier per 16-K tile, 4x fewer; STS after compute).
//   - scan/conv/ln/gate unchanged (R13-proven).
// ---------------------------------------------------------------------------

#define B_     2
#define T_     1024
#define DM     2048
#define DIN    4096
#define DCONV  4224
#define DPROJ  8384
#define NH     64
#define NTOK   (B_ * T_)   // 2048

__device__ float g_u  [(size_t)NTOK * DM];
__device__ float g_zx [(size_t)NTOK * DPROJ];
__device__ float g_xbc[(size_t)NTOK * DCONV];
__device__ float g_dt [(size_t)NTOK * NH];
__device__ float g_dA [(size_t)NTOK * NH];
__device__ float g_y  [(size_t)NTOK * DIN];

__device__ __forceinline__ float sigmoidf_(float v) { return 1.f / (1.f + expf(-v)); }

// ---- packed f32x2 helpers (FFMA2) -----------------------------------------
#define FMAF2(d, a, b, c) \
    asm("fma.rn.f32x2 %0, %1, %2, %3;" : "=l"(d) : "l"(a), "l"(b), "l"(c))
#define MULF2(d, a, b) \
    asm("mul.rn.f32x2 %0, %1, %2;" : "=l"(d) : "l"(a), "l"(b))
__device__ __forceinline__ unsigned long long packdup(float x) {
    unsigned long long r;
    uint32_t xi = __float_as_uint(x);
    asm("mov.b64 %0, {%1,%1};" : "=l"(r) : "r"(xi));
    return r;
}
__device__ __forceinline__ float2 unpack2(unsigned long long v) {
    uint32_t lo, hi;
    asm("mov.b64 {%0,%1}, %2;" : "=r"(lo), "=r"(hi) : "l"(v));
    return make_float2(__uint_as_float(lo), __uint_as_float(hi));
}

// ---- cp.async helpers (scan) ----------------------------------------------
__device__ __forceinline__ uint32_t smem_u32(const void* p) {
    return (uint32_t)__cvta_generic_to_shared(p);
}
#define CPA4(dst, src) asm volatile("cp.async.ca.shared.global [%0], [%1], 4;" :: "r"(dst), "l"(src))
#define CPA_COMMIT()   asm volatile("cp.async.commit_group;")
#define CPA_WAIT2()    asm volatile("cp.async.wait_group 2;")

// ---------------------------------------------------------------------------
// LayerNorm: one block per token row (D=2048)
// ---------------------------------------------------------------------------
__global__ void ln_kernel(const float* __restrict__ x,
                          const float* __restrict__ w,
                          const float* __restrict__ bb) {
    int r = blockIdx.x;
    const float* xr = x + (size_t)r * DM;
    float s = 0.f, s2 = 0.f;
    for (int i = threadIdx.x; i < DM; i += blockDim.x) {
        float v = xr[i]; s += v; s2 += v * v;
    }
    __shared__ float shs[32], shs2[32];
    int lane = threadIdx.x & 31, wid = threadIdx.x >> 5;
#pragma unroll
    for (int o = 16; o; o >>= 1) {
        s  += __shfl_xor_sync(0xffffffffu, s, o);
        s2 += __shfl_xor_sync(0xffffffffu, s2, o);
    }
    if (lane == 0) { shs[wid] = s; shs2[wid] = s2; }
    __syncthreads();
    __shared__ float mu_s, inv_s;
    if (threadIdx.x == 0) {
        float ts = 0.f, ts2 = 0.f;
        int nw = blockDim.x >> 5;
        for (int i = 0; i < nw; i++) { ts += shs[i]; ts2 += shs2[i]; }
        float mu = ts / DM;
        float var = ts2 / DM - mu * mu;
        mu_s = mu;
        inv_s = rsqrtf(var + 1e-5f);
    }
    __syncthreads();
    float mu = mu_s, inv = inv_s;
    for (int i = threadIdx.x; i < DM; i += blockDim.x)
        g_u[(size_t)r * DM + i] = (xr[i] - mu) * inv * w[i] + bb[i];
}

// ---------------------------------------------------------------------------
// Persistent SGEMM NT, FFMA2, BK=16, double-buffered smem (1 barrier/tile).
// C[m,n] = sum_k A[m,k] * Bw[n,k] (+Res[m,n]); CTA tile 128x128, 256 thr,
// 8x8 microtile (acc as 8x4 f32x2 pairs). Each CTA strides over all tiles.
// ---------------------------------------------------------------------------
template<bool GUARD_N, bool RES>
__device__ __forceinline__ void sgemm_body(const float* __restrict__ A,
                                           const float* __restrict__ Bw,
                                           const float* __restrict__ Res,
                                           float* __restrict__ C,
                                           int N, int K, int nbx, int ntiles) {
    __shared__ __align__(16) float As[2][16][128];
    __shared__ __align__(16) float Bs[2][16][128];

    const int tid = threadIdx.x;
    const int row = tid >> 1;          // 0..127
    const int ch  = (tid & 1) * 4;     // 0 or 4
    const int tx  = tid & 15;
    const int ty  = tid >> 4;
    const int nt  = K >> 4;            // 16-K tiles

    for (int tile = blockIdx.x; tile < ntiles; tile += gridDim.x) {
        const int m0 = (tile / nbx) * 128;
        const int n0 = (tile % nbx) * 128;

        unsigned long long acc2[8][4];
#pragma unroll
        for (int i = 0; i < 8; i++)
#pragma unroll
            for (int j = 0; j < 4; j++) acc2[i][j] = 0ull;

        int brow = n0 + row;
        bool bval = true;
        if (GUARD_N && brow >= N) { brow = 0; bval = false; }

        const float* Ap = A  + (size_t)(m0 + row) * K + ch;
        const float* Bp = Bw + (size_t)brow * K + ch;

        // prime tile 0
        float4 a0 = *reinterpret_cast<const float4*>(Ap);
        float4 a1 = *reinterpret_cast<const float4*>(Ap + 8);
        float4 b0 = *reinterpret_cast<const float4*>(Bp);
        float4 b1 = *reinterpret_cast<const float4*>(Bp + 8);
        if (GUARD_N && !bval) {
            b0 = make_float4(0.f, 0.f, 0.f, 0.f);
            b1 = b0;
        }
#pragma unroll
        for (int j = 0; j < 4; j++) {
            As[0][ch + j][row]     = (&a0.x)[j];
            As[0][ch + 8 + j][row] = (&a1.x)[j];
            Bs[0][ch + j][row]     = (&b0.x)[j];
            Bs[0][ch + 8 + j][row] = (&b1.x)[j];
        }
        __syncthreads();

        for (int kt = 0; kt < nt; kt++) {
            int cur = kt & 1;
            if (kt + 1 < nt) {     // issue next-tile LDGs; covered by compute
                int k0 = (kt + 1) << 4;
                a0 = *reinterpret_cast<const float4*>(Ap + k0);
                a1 = *reinterpret_cast<const float4*>(Ap + k0 + 8);
                b0 = *reinterpret_cast<const float4*>(Bp + k0);
                b1 = *reinterpret_cast<const float4*>(Bp + k0 + 8);
                if (GUARD_N && !bval) {
                    b0 = make_float4(0.f, 0.f, 0.f, 0.f);
                    b1 = b0;
                }
            }
#pragma unroll
            for (int kk = 0; kk < 16; kk++) {
                float a[8];
                float4 t;
                t = *reinterpret_cast<const float4*>(&As[cur][kk][ty * 4]);
                a[0] = t.x; a[1] = t.y; a[2] = t.z; a[3] = t.w;
                t = *reinterpret_cast<const float4*>(&As[cur][kk][ty * 4 + 64]);
                a[4] = t.x; a[5] = t.y; a[6] = t.z; a[7] = t.w;
                ulonglong2 bv0 = *reinterpret_cast<const ulonglong2*>(&Bs[cur][kk][tx * 4]);
                ulonglong2 bv1 = *reinterpret_cast<const ulonglong2*>(&Bs[cur][kk][tx * 4 + 64]);
                unsigned long long q0 = bv0.x, q1 = bv0.y, q2 = bv1.x, q3 = bv1.y;
#pragma unroll
                for (int i = 0; i < 8; i++) {
                    unsigned long long a2 = packdup(a[i]);
                    FMAF2(acc2[i][0], a2, q0, acc2[i][0]);
                    FMAF2(acc2[i][1], a2, q1, acc2[i][1]);
                    FMAF2(acc2[i][2], a2, q2, acc2[i][2]);
                    FMAF2(acc2[i][3], a2, q3, acc2[i][3]);
                }
            }
            if (kt + 1 < nt) {
                int nb = cur ^ 1;
#pragma unroll
                for (int j = 0; j < 4; j++) {
                    As[nb][ch + j][row]     = (&a0.x)[j];
                    As[nb][ch + 8 + j][row] = (&a1.x)[j];
                    Bs[nb][ch + j][row]     = (&b0.x)[j];
                    Bs[nb][ch + 8 + j][row] = (&b1.x)[j];
                }
            }
            __syncthreads();
        }

        // epilogue
#pragma unroll
        for (int ih = 0; ih < 2; ih++) {
#pragma unroll
            for (int ii = 0; ii < 4; ii++) {
                int i = ih * 4 + ii;
                int m = m0 + ih * 64 + ty * 4 + ii;
#pragma unroll
                for (int jh = 0; jh < 2; jh++) {
                    int n = n0 + jh * 64 + tx * 4;
                    if (GUARD_N && n >= N) continue;   // N % 4 == 0
                    float2 p0 = unpack2(acc2[i][jh * 2 + 0]);
                    float2 p1 = unpack2(acc2[i][jh * 2 + 1]);
                    float4 v = make_float4(p0.x, p0.y, p1.x, p1.y);
                    if (RES) {
                        float4 rv = *reinterpret_cast<const float4*>(Res + (size_t)m * N + n);
                        v.x += rv.x; v.y += rv.y; v.z += rv.z; v.w += rv.w;
                    }
                    *reinterpret_cast<float4*>(C + (size_t)m * N + n) = v;
                }
            }
        }
    }
}

#define G1_NBX   66              // ceil(8384/128)
#define G1_TILES (G1_NBX * 16)   // 1056
#define G2_NBX   16
#define G2_TILES (G2_NBX * 16)   // 256
#define G1_GRID  296             // 2 CTAs/SM x 148 SMs
#define G2_GRID  256

__global__ __launch_bounds__(256, 2)
void gemm1_kernel(const float* __restrict__ W) {
    sgemm_body<true, false>(g_u, W, nullptr, g_zx, DPROJ, DM, G1_NBX, G1_TILES);
}

__global__ __launch_bounds__(256, 2)
void gemm2_kernel(const float* __restrict__ W,
                  const float* __restrict__ Res,
                  float* __restrict__ C) {
    sgemm_body<false, true>(g_y, W, Res, C, DM, DIN, G2_NBX, G2_TILES);
}

// ---------------------------------------------------------------------------
// Depthwise causal conv (k=4) + SiLU. 32 t-chunks per batch.
// ---------------------------------------------------------------------------
#define CCH 32
__global__ void conv_kernel(const float* __restrict__ cw,
                            const float* __restrict__ cb) {
    int c = blockIdx.x * blockDim.x + threadIdx.x;
    if (c >= DCONV) return;
    int b = blockIdx.y >> 5;
    int chunk = blockIdx.y & 31;
    int t0 = chunk * CCH;
    float w0 = cw[c * 4 + 0], w1 = cw[c * 4 + 1];
    float w2 = cw[c * 4 + 2], w3 = cw[c * 4 + 3];
    float bias = cb[c];
    const float* src = g_zx + (size_t)b * T_ * DPROJ + DIN + c;
    float* dst = g_xbc + (size_t)b * T_ * DCONV + c;
    float x0 = (t0 >= 3) ? src[(size_t)(t0 - 3) * DPROJ] : 0.f;
    float x1 = (t0 >= 2) ? src[(size_t)(t0 - 2) * DPROJ] : 0.f;
    float x2 = (t0 >= 1) ? src[(size_t)(t0 - 1) * DPROJ] : 0.f;
    for (int t = t0; t < t0 + CCH; t++) {
        float x3 = src[(size_t)t * DPROJ];
        float v = bias + x0 * w0 + x1 * w1 + x2 * w2 + x3 * w3;
        v = v * sigmoidf_(v);
        dst[(size_t)t * DCONV] = v;
        x0 = x1; x1 = x2; x2 = x3;
    }
}

// ---------------------------------------------------------------------------
// dt = softplus(dt_raw + dt_bias), dA = exp(dt * -exp(A_log))
// ---------------------------------------------------------------------------
__global__ void dt_kernel(const float* __restrict__ dt_bias,
                          const float* __restrict__ A_log) {
    int r = blockIdx.x;
    int h = threadIdx.x;   // 64
    float raw = g_zx[(size_t)r * DPROJ + DIN + DCONV + h] + dt_bias[h];
    float dtv = (raw > 20.f) ? raw : log1pf(expf(raw));
    float Av = -expf(A_log[h]);
    g_dt[r * NH + h] = dtv;
    g_dA[r * NH + h] = expf(dtv * Av);
}

// ---------------------------------------------------------------------------
// Sequential selective scan, FFMA2 core, 4-deep cp.async prefetch ring.
// (R13-proven.)
// ---------------------------------------------------------------------------
__global__ __launch_bounds__(64)
void scan_kernel(const float* __restrict__ Dvec) {
    int bh = blockIdx.x;
    int b = bh >> 6, hh = bh & 63;
    int p = threadIdx.x;

    __shared__ __align__(16) float sB[4][64];
    __shared__ __align__(16) float sC[4][64];
    __shared__ __align__(16) float sX[4][64];
    __shared__ __align__(8)  float sS[4][2];

    unsigned long long st2[32];
#pragma unroll
    for (int n = 0; n < 32; n++) st2[n] = 0ull;
    float Dh = Dvec[hh];

    const size_t base = (size_t)b * T_ * DCONV;
    const int rr0 = b * T_;

    auto prefetch = [&](int t) {
        size_t rq = base + (size_t)t * DCONV;
        int bf = t & 3;
        CPA4(smem_u32(&sX[bf][p]), g_xbc + rq + hh * 64 + p);
        CPA4(smem_u32(&sB[bf][p]), g_xbc + rq + 4096 + p);
        CPA4(smem_u32(&sC[bf][p]), g_xbc + rq + 4160 + p);
        if (p < 2) {
            const float* sp = (p == 0) ? (g_dA + (rr0 + t) * NH + hh)
                                       : (g_dt + (rr0 + t) * NH + hh);
            CPA4(smem_u32(&sS[bf][p]), sp);
        }
    };

    prefetch(0); CPA_COMMIT();
    prefetch(1); CPA_COMMIT();
    prefetch(2); CPA_COMMIT();

    for (int t = 0; t < T_; t++) {
        int bf = t & 3;
        CPA_WAIT2();
        __syncthreads();
        if (t + 3 < T_) prefetch(t + 3);
        CPA_COMMIT();

        float dAv = sS[bf][0];
        float dtx = sS[bf][1] * sX[bf][p];
        unsigned long long dA2  = packdup(dAv);
        unsigned long long dtx2 = packdup(dtx);
        unsigned long long a4[4] = {0ull, 0ull, 0ull, 0ull};
#pragma unroll
        for (int q = 0; q < 16; q++) {
            ulonglong2 b2 = *reinterpret_cast<const ulonglong2*>(&sB[bf][q * 4]);
            ulonglong2 c2 = *reinterpret_cast<const ulonglong2*>(&sC[bf][q * 4]);
            unsigned long long t0, t1;
            MULF2(t0, dtx2, b2.x);
            MULF2(t1, dtx2, b2.y);
            FMAF2(st2[q * 2 + 0], st2[q * 2 + 0], dA2, t0);
            FMAF2(st2[q * 2 + 1], st2[q * 2 + 1], dA2, t1);
            FMAF2(a4[(2 * q) & 3], st2[q * 2 + 0], c2.x, a4[(2 * q) & 3]);
            FMAF2(a4[(2 * q + 1) & 3], st2[q * 2 + 1], c2.y, a4[(2 * q + 1) & 3]);
        }
        float2 p0 = unpack2(a4[0]), p1 = unpack2(a4[1]);
        float2 p2 = unpack2(a4[2]), p3 = unpack2(a4[3]);
        float accs = ((p0.x + p0.y) + (p1.x + p1.y)) + ((p2.x + p2.y) + (p3.x + p3.y));
        g_y[(size_t)(b * T_ + t) * DIN + hh * 64 + p] = accs + Dh * sX[bf][p];
    }
}

// ---------------------------------------------------------------------------
// y = y * silu(z); y = y * rsqrt(mean(y^2)+eps) * norm_w. Block per token.
// ---------------------------------------------------------------------------
__global__ void gate_rms_kernel(const float* __restrict__ norm_w) {
    int r = blockIdx.x;
    float ss = 0.f;
    for (int i = threadIdx.x; i < DIN; i += blockDim.x) {
        float zv = g_zx[(size_t)r * DPROJ + i];
        float g = g_y[(size_t)r * DIN + i] * zv * sigmoidf_(zv);
        g_y[(size_t)r * DIN + i] = g;
        ss += g * g;
    }
    __shared__ float sh[32];
    int lane = threadIdx.x & 31, wid = threadIdx.x >> 5;
#pragma unroll
    for (int o = 16; o; o >>= 1) ss += __shfl_xor_sync(0xffffffffu, ss, o);
    if (lane == 0) sh[wid] = ss;
    __syncthreads();
    __shared__ float sc;
    if (threadIdx.x == 0) {
        float tot = 0.f;
        int nw = blockDim.x >> 5;
        for (int i = 0; i < nw; i++) tot += sh[i];
        sc = rsqrtf(tot / DIN + 1e-5f);
    }
    __syncthreads();
    float s = sc;
    for (int i = threadIdx.x; i < DIN; i += blockDim.x)
        g_y[(size_t)r * DIN + i] *= s * norm_w[i];
}

// ---------------------------------------------------------------------------
// launch
// ---------------------------------------------------------------------------
extern "C" void kernel_launch(void* const* d_in, const int* in_sizes, int n_in,
                              void* d_out, int out_size) {
    const float* x          = (const float*)d_in[0];
    const float* ln_w       = (const float*)d_in[1];
    const float* ln_b       = (const float*)d_in[2];
    const float* in_proj_w  = (const float*)d_in[3];
    const float* conv_w     = (const float*)d_in[4];
    const float* conv_b     = (const float*)d_in[5];
    const float* dt_bias    = (const float*)d_in[6];
    const float* A_log      = (const float*)d_in[7];
    const float* Dv         = (const float*)d_in[8];
    const float* norm_w     = (const float*)d_in[9];
    const float* out_proj_w = (const float*)d_in[10];
    float* out = (float*)d_out;

    ln_kernel<<<NTOK, 256>>>(x, ln_w, ln_b);
    gemm1_kernel<<<G1_GRID, 256>>>(in_proj_w);
    conv_kernel<<<dim3((DCONV + 255) / 256, B_ * 32), 256>>>(conv_w, conv_b);
    dt_kernel<<<NTOK, NH>>>(dt_bias, A_log);
    scan_kernel<<<B_ * NH, 64>>>(Dv);
    gate_rms_kernel<<<NTOK, 256>>>(norm_w);
    gemm2_kernel<<<G2_GRID, 256>>>(out_proj_w, x, out);
}

// round 17
// speedup vs baseline: 1.0645x; 1.0645x over previous
#include <cuda_runtime.h>
#include <math.h>
#include <stdint.h>

// ---------------------------------------------------------------------------
// Mamba2 block, B=2, T=1024, D_MODEL=2048, D_STATE=64, HEADDIM=64
// R16: R13 pipeline (proven 2458us) with ONE delta:
//   gemm1 persistent (grid=296) with m-major tile striping so the concurrent
//   CTA set covers all m-blocks x ~19 n-blocks -> weights stay L2-resident
//   and the 3.57-wave tail disappears. Inner loop is byte-identical to R13
//   (BK=8, 8-reg lookahead, 2 barriers — no register-pressure change).
// gemm2 (single wave) and scan/conv/ln/gate unchanged.
// ---------------------------------------------------------------------------

#define B_     2
#define T_     1024
#define DM     2048
#define DIN    4096
#define DCONV  4224
#define DPROJ  8384
#define NH     64
#define NTOK   (B_ * T_)   // 2048

__device__ float g_u  [(size_t)NTOK * DM];
__device__ float g_zx [(size_t)NTOK * DPROJ];
__device__ float g_xbc[(size_t)NTOK * DCONV];
__device__ float g_dt [(size_t)NTOK * NH];
__device__ float g_dA [(size_t)NTOK * NH];
__device__ float g_y  [(size_t)NTOK * DIN];

__device__ __forceinline__ float sigmoidf_(float v) { return 1.f / (1.f + expf(-v)); }

// ---- packed f32x2 helpers (FFMA2) -----------------------------------------
#define FMAF2(d, a, b, c) \
    asm("fma.rn.f32x2 %0, %1, %2, %3;" : "=l"(d) : "l"(a), "l"(b), "l"(c))
#define MULF2(d, a, b) \
    asm("mul.rn.f32x2 %0, %1, %2;" : "=l"(d) : "l"(a), "l"(b))
__device__ __forceinline__ unsigned long long packdup(float x) {
    unsigned long long r;
    uint32_t xi = __float_as_uint(x);
    asm("mov.b64 %0, {%1,%1};" : "=l"(r) : "r"(xi));
    return r;
}
__device__ __forceinline__ float2 unpack2(unsigned long long v) {
    uint32_t lo, hi;
    asm("mov.b64 {%0,%1}, %2;" : "=r"(lo), "=r"(hi) : "l"(v));
    return make_float2(__uint_as_float(lo), __uint_as_float(hi));
}

// ---- cp.async helpers (scan) ----------------------------------------------
__device__ __forceinline__ uint32_t smem_u32(const void* p) {
    return (uint32_t)__cvta_generic_to_shared(p);
}
#define CPA4(dst, src) asm volatile("cp.async.ca.shared.global [%0], [%1], 4;" :: "r"(dst), "l"(src))
#define CPA_COMMIT()   asm volatile("cp.async.commit_group;")
#define CPA_WAIT2()    asm volatile("cp.async.wait_group 2;")

// ---------------------------------------------------------------------------
// LayerNorm: one block per token row (D=2048)
// ---------------------------------------------------------------------------
__global__ void ln_kernel(const float* __restrict__ x,
                          const float* __restrict__ w,
                          const float* __restrict__ bb) {
    int r = blockIdx.x;
    const float* xr = x + (size_t)r * DM;
    float s = 0.f, s2 = 0.f;
    for (int i = threadIdx.x; i < DM; i += blockDim.x) {
        float v = xr[i]; s += v; s2 += v * v;
    }
    __shared__ float shs[32], shs2[32];
    int lane = threadIdx.x & 31, wid = threadIdx.x >> 5;
#pragma unroll
    for (int o = 16; o; o >>= 1) {
        s  += __shfl_xor_sync(0xffffffffu, s, o);
        s2 += __shfl_xor_sync(0xffffffffu, s2, o);
    }
    if (lane == 0) { shs[wid] = s; shs2[wid] = s2; }
    __syncthreads();
    __shared__ float mu_s, inv_s;
    if (threadIdx.x == 0) {
        float ts = 0.f, ts2 = 0.f;
        int nw = blockDim.x >> 5;
        for (int i = 0; i < nw; i++) { ts += shs[i]; ts2 += shs2[i]; }
        float mu = ts / DM;
        float var = ts2 / DM - mu * mu;
        mu_s = mu;
        inv_s = rsqrtf(var + 1e-5f);
    }
    __syncthreads();
    float mu = mu_s, inv = inv_s;
    for (int i = threadIdx.x; i < DM; i += blockDim.x)
        g_u[(size_t)r * DM + i] = (xr[i] - mu) * inv * w[i] + bb[i];
}

// ---------------------------------------------------------------------------
// SGEMM NT tile body — byte-identical inner loop to R13 (BK=8, 8-reg
// lookahead, 2 barriers/tile, FFMA2 microtile 8x8).
// ---------------------------------------------------------------------------
template<bool GUARD_N, bool RES>
__device__ __forceinline__ void sgemm_tile(const float* __restrict__ A,
                                           const float* __restrict__ Bw,
                                           const float* __restrict__ Res,
                                           float* __restrict__ C,
                                           int N, int K, int m0, int n0) {
    __shared__ __align__(16) float As[8][128];
    __shared__ __align__(16) float Bs[8][128];

    const int tid = threadIdx.x;
    const int lrow = tid >> 1;
    const int lcol = (tid & 1) << 2;
    const int tx = tid & 15;
    const int ty = tid >> 4;

    unsigned long long acc2[8][4];
#pragma unroll
    for (int i = 0; i < 8; i++)
#pragma unroll
        for (int j = 0; j < 4; j++) acc2[i][j] = 0ull;

    int brow = n0 + lrow;
    bool bval = true;
    if (GUARD_N && brow >= N) { brow = 0; bval = false; }

    const float* Ap = A  + (size_t)(m0 + lrow) * K + lcol;
    const float* Bp = Bw + (size_t)brow * K + lcol;

    float4 av = *reinterpret_cast<const float4*>(Ap);
    float4 bv = *reinterpret_cast<const float4*>(Bp);
    if (GUARD_N && !bval) bv = make_float4(0.f, 0.f, 0.f, 0.f);

    for (int k0 = 0; k0 < K; k0 += 8) {
        __syncthreads();
        As[lcol + 0][lrow] = av.x; As[lcol + 1][lrow] = av.y;
        As[lcol + 2][lrow] = av.z; As[lcol + 3][lrow] = av.w;
        Bs[lcol + 0][lrow] = bv.x; Bs[lcol + 1][lrow] = bv.y;
        Bs[lcol + 2][lrow] = bv.z; Bs[lcol + 3][lrow] = bv.w;
        __syncthreads();

        if (k0 + 8 < K) {
            av = *reinterpret_cast<const float4*>(Ap + k0 + 8);
            bv = *reinterpret_cast<const float4*>(Bp + k0 + 8);
            if (GUARD_N && !bval) bv = make_float4(0.f, 0.f, 0.f, 0.f);
        }

#pragma unroll
        for (int kk = 0; kk < 8; kk++) {
            float a[8];
            float4 t;
            t = *reinterpret_cast<const float4*>(&As[kk][ty * 4]);
            a[0] = t.x; a[1] = t.y; a[2] = t.z; a[3] = t.w;
            t = *reinterpret_cast<const float4*>(&As[kk][ty * 4 + 64]);
            a[4] = t.x; a[5] = t.y; a[6] = t.z; a[7] = t.w;
            ulonglong2 bv0 = *reinterpret_cast<const ulonglong2*>(&Bs[kk][tx * 4]);
            ulonglong2 bv1 = *reinterpret_cast<const ulonglong2*>(&Bs[kk][tx * 4 + 64]);
            unsigned long long b0 = bv0.x, b1 = bv0.y, b2 = bv1.x, b3 = bv1.y;
#pragma unroll
            for (int i = 0; i < 8; i++) {
                unsigned long long a2 = packdup(a[i]);
                FMAF2(acc2[i][0], a2, b0, acc2[i][0]);
                FMAF2(acc2[i][1], a2, b1, acc2[i][1]);
                FMAF2(acc2[i][2], a2, b2, acc2[i][2]);
                FMAF2(acc2[i][3], a2, b3, acc2[i][3]);
            }
        }
    }
    __syncthreads();   // protect As/Bs reuse across persistent tile loop

#pragma unroll
    for (int ih = 0; ih < 2; ih++) {
#pragma unroll
        for (int ii = 0; ii < 4; ii++) {
            int i = ih * 4 + ii;
            int m = m0 + ih * 64 + ty * 4 + ii;
#pragma unroll
            for (int jh = 0; jh < 2; jh++) {
                int n = n0 + jh * 64 + tx * 4;
                if (GUARD_N && n >= N) continue;   // N % 4 == 0
                float2 p0 = unpack2(acc2[i][jh * 2 + 0]);
                float2 p1 = unpack2(acc2[i][jh * 2 + 1]);
                float4 v = make_float4(p0.x, p0.y, p1.x, p1.y);
                if (RES) {
                    float4 rv = *reinterpret_cast<const float4*>(Res + (size_t)m * N + n);
                    v.x += rv.x; v.y += rv.y; v.z += rv.z; v.w += rv.w;
                }
                *reinterpret_cast<float4*>(C + (size_t)m * N + n) = v;
            }
        }
    }
}

#define G1_GRID 296   // 2 CTAs/SM x 148 SMs

// gemm1: persistent, m-major-within-n striping (tile%16 = m-block,
// tile/16 = n-block) -> concurrent set = all m x ~19 n -> L2-resident weights.
__global__ __launch_bounds__(256, 2)
void gemm1_kernel(const float* __restrict__ W) {
    const int ntiles = 16 * 66;   // 1056
    for (int tile = blockIdx.x; tile < ntiles; tile += G1_GRID) {
        int m0 = (tile & 15) * 128;
        int n0 = (tile >> 4) * 128;
        sgemm_tile<true, false>(g_u, W, nullptr, g_zx, DPROJ, DM, m0, n0);
    }
}

// gemm2: 256 CTAs = single wave; non-persistent (R13-proven).
__global__ __launch_bounds__(256, 2)
void gemm2_kernel(const float* __restrict__ W,
                  const float* __restrict__ Res,
                  float* __restrict__ C) {
    sgemm_tile<false, true>(g_y, W, Res, C, DM, DIN,
                            blockIdx.y * 128, blockIdx.x * 128);
}

// ---------------------------------------------------------------------------
// Depthwise causal conv (k=4) + SiLU. 32 t-chunks per batch.
// ---------------------------------------------------------------------------
#define CCH 32
__global__ void conv_kernel(const float* __restrict__ cw,
                            const float* __restrict__ cb) {
    int c = blockIdx.x * blockDim.x + threadIdx.x;
    if (c >= DCONV) return;
    int b = blockIdx.y >> 5;
    int chunk = blockIdx.y & 31;
    int t0 = chunk * CCH;
    float w0 = cw[c * 4 + 0], w1 = cw[c * 4 + 1];
    float w2 = cw[c * 4 + 2], w3 = cw[c * 4 + 3];
    float bias = cb[c];
    const float* src = g_zx + (size_t)b * T_ * DPROJ + DIN + c;
    float* dst = g_xbc + (size_t)b * T_ * DCONV + c;
    float x0 = (t0 >= 3) ? src[(size_t)(t0 - 3) * DPROJ] : 0.f;
    float x1 = (t0 >= 2) ? src[(size_t)(t0 - 2) * DPROJ] : 0.f;
    float x2 = (t0 >= 1) ? src[(size_t)(t0 - 1) * DPROJ] : 0.f;
    for (int t = t0; t < t0 + CCH; t++) {
        float x3 = src[(size_t)t * DPROJ];
        float v = bias + x0 * w0 + x1 * w1 + x2 * w2 + x3 * w3;
        v = v * sigmoidf_(v);
        dst[(size_t)t * DCONV] = v;
        x0 = x1; x1 = x2; x2 = x3;
    }
}

// ---------------------------------------------------------------------------
// dt = softplus(dt_raw + dt_bias), dA = exp(dt * -exp(A_log))
// ---------------------------------------------------------------------------
__global__ void dt_kernel(const float* __restrict__ dt_bias,
                          const float* __restrict__ A_log) {
    int r = blockIdx.x;
    int h = threadIdx.x;   // 64
    float raw = g_zx[(size_t)r * DPROJ + DIN + DCONV + h] + dt_bias[h];
    float dtv = (raw > 20.f) ? raw : log1pf(expf(raw));
    float Av = -expf(A_log[h]);
    g_dt[r * NH + h] = dtv;
    g_dA[r * NH + h] = expf(dtv * Av);
}

// ---------------------------------------------------------------------------
// Sequential selective scan, FFMA2 core, 4-deep cp.async prefetch ring.
// (R13-proven.)
// ---------------------------------------------------------------------------
__global__ __launch_bounds__(64)
void scan_kernel(const float* __restrict__ Dvec) {
    int bh = blockIdx.x;
    int b = bh >> 6, hh = bh & 63;
    int p = threadIdx.x;

    __shared__ __align__(16) float sB[4][64];
    __shared__ __align__(16) float sC[4][64];
    __shared__ __align__(16) float sX[4][64];
    __shared__ __align__(8)  float sS[4][2];

    unsigned long long st2[32];
#pragma unroll
    for (int n = 0; n < 32; n++) st2[n] = 0ull;
    float Dh = Dvec[hh];

    const size_t base = (size_t)b * T_ * DCONV;
    const int rr0 = b * T_;

    auto prefetch = [&](int t) {
        size_t rq = base + (size_t)t * DCONV;
        int bf = t & 3;
        CPA4(smem_u32(&sX[bf][p]), g_xbc + rq + hh * 64 + p);
        CPA4(smem_u32(&sB[bf][p]), g_xbc + rq + 4096 + p);
        CPA4(smem_u32(&sC[bf][p]), g_xbc + rq + 4160 + p);
        if (p < 2) {
            const float* sp = (p == 0) ? (g_dA + (rr0 + t) * NH + hh)
                                       : (g_dt + (rr0 + t) * NH + hh);
            CPA4(smem_u32(&sS[bf][p]), sp);
        }
    };

    prefetch(0); CPA_COMMIT();
    prefetch(1); CPA_COMMIT();
    prefetch(2); CPA_COMMIT();

    for (int t = 0; t < T_; t++) {
        int bf = t & 3;
        CPA_WAIT2();
        __syncthreads();
        if (t + 3 < T_) prefetch(t + 3);
        CPA_COMMIT();

        float dAv = sS[bf][0];
        float dtx = sS[bf][1] * sX[bf][p];
        unsigned long long dA2  = packdup(dAv);
        unsigned long long dtx2 = packdup(dtx);
        unsigned long long a4[4] = {0ull, 0ull, 0ull, 0ull};
#pragma unroll
        for (int q = 0; q < 16; q++) {
            ulonglong2 b2 = *reinterpret_cast<const ulonglong2*>(&sB[bf][q * 4]);
            ulonglong2 c2 = *reinterpret_cast<const ulonglong2*>(&sC[bf][q * 4]);
            unsigned long long t0, t1;
            MULF2(t0, dtx2, b2.x);
            MULF2(t1, dtx2, b2.y);
            FMAF2(st2[q * 2 + 0], st2[q * 2 + 0], dA2, t0);
            FMAF2(st2[q * 2 + 1], st2[q * 2 + 1], dA2, t1);
            FMAF2(a4[(2 * q) & 3], st2[q * 2 + 0], c2.x, a4[(2 * q) & 3]);
            FMAF2(a4[(2 * q + 1) & 3], st2[q * 2 + 1], c2.y, a4[(2 * q + 1) & 3]);
        }
        float2 p0 = unpack2(a4[0]), p1 = unpack2(a4[1]);
        float2 p2 = unpack2(a4[2]), p3 = unpack2(a4[3]);
        float accs = ((p0.x + p0.y) + (p1.x + p1.y)) + ((p2.x + p2.y) + (p3.x + p3.y));
        g_y[(size_t)(b * T_ + t) * DIN + hh * 64 + p] = accs + Dh * sX[bf][p];
    }
}

// ---------------------------------------------------------------------------
// y = y * silu(z); y = y * rsqrt(mean(y^2)+eps) * norm_w. Block per token.
// ---------------------------------------------------------------------------
__global__ void gate_rms_kernel(const float* __restrict__ norm_w) {
    int r = blockIdx.x;
    float ss = 0.f;
    for (int i = threadIdx.x; i < DIN; i += blockDim.x) {
        float zv = g_zx[(size_t)r * DPROJ + i];
        float g = g_y[(size_t)r * DIN + i] * zv * sigmoidf_(zv);
        g_y[(size_t)r * DIN + i] = g;
        ss += g * g;
    }
    __shared__ float sh[32];
    int lane = threadIdx.x & 31, wid = threadIdx.x >> 5;
#pragma unroll
    for (int o = 16; o; o >>= 1) ss += __shfl_xor_sync(0xffffffffu, ss, o);
    if (lane == 0) sh[wid] = ss;
    __syncthreads();
    __shared__ float sc;
    if (threadIdx.x == 0) {
        float tot = 0.f;
        int nw = blockDim.x >> 5;
        for (int i = 0; i < nw; i++) tot += sh[i];
        sc = rsqrtf(tot / DIN + 1e-5f);
    }
    __syncthreads();
    float s = sc;
    for (int i = threadIdx.x; i < DIN; i += blockDim.x)
        g_y[(size_t)r * DIN + i] *= s * norm_w[i];
}

// ---------------------------------------------------------------------------
// launch
// ---------------------------------------------------------------------------
extern "C" void kernel_launch(void* const* d_in, const int* in_sizes, int n_in,
                              void* d_out, int out_size) {
    const float* x          = (const float*)d_in[0];
    const float* ln_w       = (const float*)d_in[1];
    const float* ln_b       = (const float*)d_in[2];
    const float* in_proj_w  = (const float*)d_in[3];
    const float* conv_w     = (const float*)d_in[4];
    const float* conv_b     = (const float*)d_in[5];
    const float* dt_bias    = (const float*)d_in[6];
    const float* A_log      = (const float*)d_in[7];
    const float* Dv         = (const float*)d_in[8];
    const float* norm_w     = (const float*)d_in[9];
    const float* out_proj_w = (const float*)d_in[10];
    float* out = (float*)d_out;

    ln_kernel<<<NTOK, 256>>>(x, ln_w, ln_b);
    gemm1_kernel<<<G1_GRID, 256>>>(in_proj_w);
    conv_kernel<<<dim3((DCONV + 255) / 256, B_ * 32), 256>>>(conv_w, conv_b);
    dt_kernel<<<NTOK, NH>>>(dt_bias, A_log);
    scan_kernel<<<B_ * NH, 64>>>(Dv);
    gate_rms_kernel<<<NTOK, 256>>>(norm_w);
    gemm2_kernel<<<dim3(DM / 128, NTOK / 128), 256>>>(out_proj_w, x, out);
}